// round 12
// baseline (speedup 1.0000x reference)
#include <cuda_runtime.h>

typedef unsigned long long UL;

constexpr int NB = 4, NC = 512, NSEQ = 2048, NH = 8, NDK = 64, NBH = NB * NH;

// scratch (device globals; allocation-free)
__device__ float g_Q[(size_t)NBH * NDK * NSEQ];   // [bh][d][n]
__device__ float g_K[(size_t)NBH * NDK * NSEQ];   // [bh][d][n]
__device__ float g_V[(size_t)NBH * NDK * NSEQ];   // [bh][d][n]
__device__ float g_S[(size_t)NBH * NSEQ * NSEQ];  // exp(scale*QK^T) [bh][i][j]
__device__ float g_rl[NBH * NSEQ];                // 1/colsum
__device__ float g_R[(size_t)NB * NC * NSEQ];     // attn out, c-major: [b][h*64+d][n]

__device__ __forceinline__ void fma2(UL &acc, UL a, UL b) {
    asm("fma.rn.f32x2 %0, %1, %2, %0;" : "+l"(acc) : "l"(a), "l"(b));
}
__device__ __forceinline__ float f2lo(UL v) { return __uint_as_float((unsigned)v); }
__device__ __forceinline__ float f2hi(UL v) { return __uint_as_float((unsigned)(v >> 32)); }

// store float4 v duplicated ({x,x},{y,y},{z,z},{w,w}) at float2-cols f4*4..f4*4+3
__device__ __forceinline__ void dup_store(float* row, int f4, float4 v) {
    float2* p = (float2*)row + f4 * 4;
    p[0] = make_float2(v.x, v.x); p[1] = make_float2(v.y, v.y);
    p[2] = make_float2(v.z, v.z); p[3] = make_float2(v.w, v.w);
}

// inner product: A duplicated in smem (LDS.64 -> packed dup), B packed pairs.
template <int NM, int NQ, int AS, int BS>
__device__ __forceinline__ void ginner(const float (*As2)[AS], const float (*Bs)[BS],
                                       UL (*acc)[NQ], int tx, int row0) {
#pragma unroll
    for (int kk = 0; kk < 16; kk++) {
        UL b2[NQ];
#pragma unroll
        for (int q = 0; q < NQ; q++) b2[q] = *(const UL*)&Bs[kk][2 * (tx + 16 * q)];
#pragma unroll
        for (int m = 0; m < NM; m++) {
            UL a2 = *(const UL*)&As2[kk][2 * (row0 + m)];
#pragma unroll
            for (int q = 0; q < NQ; q++) fma2(acc[m][q], a2, b2[q]);
        }
    }
}

// ---------- K1: QKV projection; scatter into Q/K/V [bh][d][n] ----------
__global__ void __launch_bounds__(256) k1_qkv(const float* __restrict__ x,
                                              const float* __restrict__ Wp,
                                              const float* __restrict__ bp) {
    __shared__ float As2[16][258];  // [cc][2*nn] dup'd x tile
    __shared__ float Bs[16][132];   // [cc][oo]   Wp transposed
    const int tid = threadIdx.x, tx = tid & 15, ty = tid >> 4;
    const int n0 = blockIdx.x * 128, o0 = blockIdx.y * 128, b = blockIdx.z;
    const float* xb = x + (size_t)b * NC * NSEQ;

    UL acc[8][4];
#pragma unroll
    for (int m = 0; m < 8; m++)
#pragma unroll
        for (int q = 0; q < 4; q++) acc[m][q] = 0ull;

    for (int c0 = 0; c0 < NC; c0 += 16) {
#pragma unroll
        for (int r = 0; r < 2; r++) {
            int idx = tid + 256 * r, cc = idx >> 5, f4 = idx & 31;
            float4 v = *(const float4*)(xb + (size_t)(c0 + cc) * NSEQ + n0 + f4 * 4);
            dup_store(As2[cc], f4, v);
        }
#pragma unroll
        for (int r = 0; r < 2; r++) {
            int idx = tid + 256 * r, oo = idx >> 2, c4 = idx & 3;
            float4 w = *(const float4*)(Wp + (size_t)(o0 + oo) * NC + c0 + c4 * 4);
            Bs[c4 * 4 + 0][oo] = w.x; Bs[c4 * 4 + 1][oo] = w.y;
            Bs[c4 * 4 + 2][oo] = w.z; Bs[c4 * 4 + 3][oo] = w.w;
        }
        __syncthreads();
        ginner<8, 4, 258, 132>(As2, Bs, acc, tx, ty * 8);
        __syncthreads();
    }

    const int bh0 = blockIdx.z * NH;
#pragma unroll
    for (int q = 0; q < 4; q++)
#pragma unroll
        for (int e = 0; e < 2; e++) {
            int o = o0 + 2 * (tx + 16 * q) + e;
            int h = o / 192, rr = o - h * 192;
            float* dst; int d;
            if (rr < 64)       { dst = g_Q; d = rr; }
            else if (rr < 128) { dst = g_K; d = rr - 64; }
            else               { dst = g_V; d = rr - 128; }
            float bias = bp[o];
            float* base = dst + ((size_t)(bh0 + h) * NDK + d) * NSEQ + n0 + ty * 8;
            float4 v0, v1;
            v0.x = (e ? f2hi(acc[0][q]) : f2lo(acc[0][q])) + bias;
            v0.y = (e ? f2hi(acc[1][q]) : f2lo(acc[1][q])) + bias;
            v0.z = (e ? f2hi(acc[2][q]) : f2lo(acc[2][q])) + bias;
            v0.w = (e ? f2hi(acc[3][q]) : f2lo(acc[3][q])) + bias;
            v1.x = (e ? f2hi(acc[4][q]) : f2lo(acc[4][q])) + bias;
            v1.y = (e ? f2hi(acc[5][q]) : f2lo(acc[5][q])) + bias;
            v1.z = (e ? f2hi(acc[6][q]) : f2lo(acc[6][q])) + bias;
            v1.w = (e ? f2hi(acc[7][q]) : f2lo(acc[7][q])) + bias;
            *(float4*)base = v0; *(float4*)(base + 4) = v1;
        }
}

// ---------- K2a: S = exp(scale * Q^T K) ----------
__global__ void __launch_bounds__(256) k2a_scores() {
    __shared__ float As2[16][258];  // [dd][2*ii] dup'd Q tile
    __shared__ float Bs[16][132];   // [dd][jj]   K tile
    const int tid = threadIdx.x, tx = tid & 15, ty = tid >> 4;
    const int j0 = blockIdx.x * 128, i0 = blockIdx.y * 128, bh = blockIdx.z;
    const float* Qb = g_Q + (size_t)bh * NDK * NSEQ;
    const float* Kb = g_K + (size_t)bh * NDK * NSEQ;

    UL acc[8][4];
#pragma unroll
    for (int m = 0; m < 8; m++)
#pragma unroll
        for (int q = 0; q < 4; q++) acc[m][q] = 0ull;

    for (int d0 = 0; d0 < NDK; d0 += 16) {
#pragma unroll
        for (int r = 0; r < 2; r++) {
            int idx = tid + 256 * r, dd = idx >> 5, f4 = idx & 31;
            float4 qv = *(const float4*)(Qb + (size_t)(d0 + dd) * NSEQ + i0 + f4 * 4);
            dup_store(As2[dd], f4, qv);
            *(float4*)&Bs[dd][f4 * 4] =
                *(const float4*)(Kb + (size_t)(d0 + dd) * NSEQ + j0 + f4 * 4);
        }
        __syncthreads();
        ginner<8, 4, 258, 132>(As2, Bs, acc, tx, ty * 8);
        __syncthreads();
    }

    float* Sb = g_S + (size_t)bh * NSEQ * NSEQ;
#pragma unroll
    for (int q = 0; q < 4; q++) {
        int jc = j0 + 2 * (tx + 16 * q);
#pragma unroll
        for (int m = 0; m < 8; m++) {
            int i = i0 + ty * 8 + m;
            float2 ev;
            ev.x = __expf(f2lo(acc[m][q]) * 0.125f);
            ev.y = __expf(f2hi(acc[m][q]) * 0.125f);
            *(float2*)(Sb + (size_t)i * NSEQ + jc) = ev;
        }
    }
}

// ---------- K2b: rl[j] = 1 / sum_i S[i][j] (deterministic) ----------
__global__ void __launch_bounds__(256) k2b_colsum() {
    const int bh = blockIdx.y;
    const int j = blockIdx.x * 256 + threadIdx.x;
    const float* Sb = g_S + (size_t)bh * NSEQ * NSEQ + j;
    float s0 = 0.f, s1 = 0.f, s2 = 0.f, s3 = 0.f;
    for (int i = 0; i < NSEQ; i += 4) {
        s0 += Sb[(size_t)(i + 0) * NSEQ];
        s1 += Sb[(size_t)(i + 1) * NSEQ];
        s2 += Sb[(size_t)(i + 2) * NSEQ];
        s3 += Sb[(size_t)(i + 3) * NSEQ];
    }
    g_rl[bh * NSEQ + j] = 1.0f / ((s0 + s1) + (s2 + s3));
}

// ---------- K2c: R^T[d][i] = sum_j (V[d][j]*rl[j]) * S[i][j] ----------
// broadcast = V*rl (dup'd), packed pairs over i. Output c-major into g_R.
__global__ void __launch_bounds__(256, 4) k2c_av() {
    __shared__ float As2[16][132];  // [jj][2*dd] dup'd V*rl (64 d cols)
    __shared__ float Bs[16][132];   // [jj][ii]   S transposed tile
    const int tid = threadIdx.x, tx = tid & 15, ty = tid >> 4;
    const int i0 = blockIdx.x * 128, h = blockIdx.y, b = blockIdx.z;
    const int bh = b * NH + h;
    const float* Sb  = g_S + (size_t)bh * NSEQ * NSEQ;
    const float* Vb  = g_V + (size_t)bh * NDK * NSEQ;
    const float* rlb = g_rl + bh * NSEQ;

    UL acc[4][4];
#pragma unroll
    for (int m = 0; m < 4; m++)
#pragma unroll
        for (int q = 0; q < 4; q++) acc[m][q] = 0ull;

    for (int j0 = 0; j0 < NSEQ; j0 += 16) {
        {   // V tile: 64d x 16j, scaled by rl, duplicated
            int dd = tid >> 2, j4 = tid & 3;
            float4 vv = *(const float4*)(Vb + (size_t)dd * NSEQ + j0 + j4 * 4);
            float r0 = rlb[j0 + j4 * 4 + 0], r1 = rlb[j0 + j4 * 4 + 1];
            float r2 = rlb[j0 + j4 * 4 + 2], r3 = rlb[j0 + j4 * 4 + 3];
            float v;
            v = vv.x * r0; *(float2*)&As2[j4 * 4 + 0][2 * dd] = make_float2(v, v);
            v = vv.y * r1; *(float2*)&As2[j4 * 4 + 1][2 * dd] = make_float2(v, v);
            v = vv.z * r2; *(float2*)&As2[j4 * 4 + 2][2 * dd] = make_float2(v, v);
            v = vv.w * r3; *(float2*)&As2[j4 * 4 + 3][2 * dd] = make_float2(v, v);
        }
#pragma unroll
        for (int r = 0; r < 2; r++) {  // S tile transposed: Bs[jj][ii]
            int idx = tid + 256 * r, ii = idx >> 2, j4 = idx & 3;
            float4 sv = *(const float4*)(Sb + (size_t)(i0 + ii) * NSEQ + j0 + j4 * 4);
            Bs[j4 * 4 + 0][ii] = sv.x; Bs[j4 * 4 + 1][ii] = sv.y;
            Bs[j4 * 4 + 2][ii] = sv.z; Bs[j4 * 4 + 3][ii] = sv.w;
        }
        __syncthreads();
        ginner<4, 4, 132, 132>(As2, Bs, acc, tx, ty * 4);
        __syncthreads();
    }

    float* Rb = g_R + ((size_t)b * NC + h * NDK) * NSEQ;
#pragma unroll
    for (int m = 0; m < 4; m++) {
        int d = ty * 4 + m;
#pragma unroll
        for (int q = 0; q < 4; q++) {
            float2 v; v.x = f2lo(acc[m][q]); v.y = f2hi(acc[m][q]);
            *(float2*)(Rb + (size_t)d * NSEQ + i0 + 2 * (tx + 16 * q)) = v;
        }
    }
}

// ---------- K3: out[b][c][n] = sum_k R^T[k][n] * Wo[c][k] + bo[c] + x[b][c][n] ----------
__global__ void __launch_bounds__(256) k3_out(const float* __restrict__ x,
                                              const float* __restrict__ Wo,
                                              const float* __restrict__ bo,
                                              float* __restrict__ out) {
    __shared__ float As2[16][258];  // [kk][2*nn] dup'd R^T tile (direct, c-major)
    __shared__ float Bs[16][132];   // [kk][cc]   Wo transposed
    const int tid = threadIdx.x, tx = tid & 15, ty = tid >> 4;
    const int n0 = blockIdx.x * 128, c0 = blockIdx.y * 128, b = blockIdx.z;
    const float* Rb = g_R + (size_t)b * NC * NSEQ;

    UL acc[8][4];
#pragma unroll
    for (int m = 0; m < 8; m++)
#pragma unroll
        for (int q = 0; q < 4; q++) acc[m][q] = 0ull;

    for (int k0 = 0; k0 < NC; k0 += 16) {
#pragma unroll
        for (int r = 0; r < 2; r++) {
            int idx = tid + 256 * r, kk = idx >> 5, f4 = idx & 31;
            float4 rv = *(const float4*)(Rb + (size_t)(k0 + kk) * NSEQ + n0 + f4 * 4);
            dup_store(As2[kk], f4, rv);
        }
#pragma unroll
        for (int r = 0; r < 2; r++) {
            int idx = tid + 256 * r, cc = idx >> 2, c4 = idx & 3;
            float4 wv = *(const float4*)(Wo + (size_t)(c0 + cc) * NC + k0 + c4 * 4);
            Bs[c4 * 4 + 0][cc] = wv.x; Bs[c4 * 4 + 1][cc] = wv.y;
            Bs[c4 * 4 + 2][cc] = wv.z; Bs[c4 * 4 + 3][cc] = wv.w;
        }
        __syncthreads();
        ginner<8, 4, 258, 132>(As2, Bs, acc, tx, ty * 8);
        __syncthreads();
    }

#pragma unroll
    for (int q = 0; q < 4; q++)
#pragma unroll
        for (int e = 0; e < 2; e++) {
            int c = c0 + 2 * (tx + 16 * q) + e;
            float bias = bo[c];
            const float* xr = x + ((size_t)b * NC + c) * NSEQ + n0 + ty * 8;
            float* orow = out + ((size_t)b * NC + c) * NSEQ + n0 + ty * 8;
            float4 x0 = *(const float4*)xr, x1 = *(const float4*)(xr + 4);
            float4 v0, v1;
            v0.x = (e ? f2hi(acc[0][q]) : f2lo(acc[0][q])) + bias + x0.x;
            v0.y = (e ? f2hi(acc[1][q]) : f2lo(acc[1][q])) + bias + x0.y;
            v0.z = (e ? f2hi(acc[2][q]) : f2lo(acc[2][q])) + bias + x0.z;
            v0.w = (e ? f2hi(acc[3][q]) : f2lo(acc[3][q])) + bias + x0.w;
            v1.x = (e ? f2hi(acc[4][q]) : f2lo(acc[4][q])) + bias + x1.x;
            v1.y = (e ? f2hi(acc[5][q]) : f2lo(acc[5][q])) + bias + x1.y;
            v1.z = (e ? f2hi(acc[6][q]) : f2lo(acc[6][q])) + bias + x1.z;
            v1.w = (e ? f2hi(acc[7][q]) : f2lo(acc[7][q])) + bias + x1.w;
            *(float4*)orow = v0; *(float4*)(orow + 4) = v1;
        }
}

extern "C" void kernel_launch(void* const* d_in, const int* in_sizes, int n_in,
                              void* d_out, int out_size) {
    const float* x  = (const float*)d_in[0];
    const float* Wp = (const float*)d_in[1];
    const float* bp = (const float*)d_in[2];
    const float* Wo = (const float*)d_in[3];
    const float* bo = (const float*)d_in[4];
    float* out = (float*)d_out;

    k1_qkv<<<dim3(NSEQ / 128, (3 * NH * NDK) / 128, NB), 256>>>(x, Wp, bp);
    k2a_scores<<<dim3(NSEQ / 128, NSEQ / 128, NBH), 256>>>();
    k2b_colsum<<<dim3(NSEQ / 256, NBH), 256>>>();
    k2c_av<<<dim3(NSEQ / 128, NH, NB), 256>>>();
    k3_out<<<dim3(NSEQ / 128, NC / 128, NB), 256>>>(x, Wo, bo, out);
}

// round 15
// speedup vs baseline: 1.2578x; 1.2578x over previous
#include <cuda_runtime.h>

typedef unsigned long long UL;

constexpr int NB = 4, NC = 512, NSEQ = 2048, NH = 8, NDK = 64, NBH = NB * NH;

// scratch (device globals; allocation-free)
__device__ float g_Q[(size_t)NBH * NDK * NSEQ];   // [bh][d][n]
__device__ float g_K[(size_t)NBH * NDK * NSEQ];   // [bh][d][n]
__device__ float g_V[(size_t)NBH * NDK * NSEQ];   // [bh][d][n]
__device__ float g_S[(size_t)NBH * NSEQ * NSEQ];  // exp(scale*QK^T) [bh][i][j]
__device__ float g_rl[NBH * NSEQ];                // 1/colsum
__device__ float g_R[(size_t)NB * NC * NSEQ];     // attn out, c-major: [b][h*64+d][n]

__device__ __forceinline__ UL pack_dup(float x) {
    UL r; unsigned u = __float_as_uint(x);
    asm("mov.b64 %0, {%1, %2};" : "=l"(r) : "r"(u), "r"(u));
    return r;
}
__device__ __forceinline__ void fma2(UL &acc, UL a, UL b) {
    asm("fma.rn.f32x2 %0, %1, %2, %0;" : "+l"(acc) : "l"(a), "l"(b));
}
__device__ __forceinline__ float f2lo(UL v) { return __uint_as_float((unsigned)v); }
__device__ __forceinline__ float f2hi(UL v) { return __uint_as_float((unsigned)(v >> 32)); }

// inner product: A scalar broadcast (LDS + mov-dup on alu pipe), B packed pairs (LDS.64)
template <int NM, int NQ, int AS, int BS>
__device__ __forceinline__ void ginner(const float (*As)[AS], const float (*Bs)[BS],
                                       UL (*acc)[NQ], int tx, int row0) {
#pragma unroll
    for (int kk = 0; kk < 16; kk++) {
        UL b2[NQ];
#pragma unroll
        for (int q = 0; q < NQ; q++) b2[q] = *(const UL*)&Bs[kk][2 * (tx + 16 * q)];
#pragma unroll
        for (int m = 0; m < NM; m++) {
            UL a2 = pack_dup(As[kk][row0 + m]);
#pragma unroll
            for (int q = 0; q < NQ; q++) fma2(acc[m][q], a2, b2[q]);
        }
    }
}

// ---------- K1: QKV projection; scatter into Q/K/V [bh][d][n] ----------
__global__ void __launch_bounds__(256) k1_qkv(const float* __restrict__ x,
                                              const float* __restrict__ Wp,
                                              const float* __restrict__ bp) {
    __shared__ float As[16][132];  // [cc][nn]  (x is already c-major)
    __shared__ float Bs[16][132];  // [cc][oo]  (Wp transposed on load)
    const int tid = threadIdx.x, tx = tid & 15, ty = tid >> 4;
    const int n0 = blockIdx.x * 128, o0 = blockIdx.y * 128, b = blockIdx.z;
    const float* xb = x + (size_t)b * NC * NSEQ;

    UL acc[8][4];
#pragma unroll
    for (int m = 0; m < 8; m++)
#pragma unroll
        for (int q = 0; q < 4; q++) acc[m][q] = 0ull;

    for (int c0 = 0; c0 < NC; c0 += 16) {
#pragma unroll
        for (int r = 0; r < 2; r++) {
            int idx = tid + 256 * r, cc = idx >> 5, f4 = idx & 31;
            *(float4*)&As[cc][f4 * 4] = *(const float4*)(xb + (size_t)(c0 + cc) * NSEQ + n0 + f4 * 4);
        }
#pragma unroll
        for (int r = 0; r < 2; r++) {
            int idx = tid + 256 * r, oo = idx >> 2, c4 = idx & 3;
            float4 w = *(const float4*)(Wp + (size_t)(o0 + oo) * NC + c0 + c4 * 4);
            Bs[c4 * 4 + 0][oo] = w.x; Bs[c4 * 4 + 1][oo] = w.y;
            Bs[c4 * 4 + 2][oo] = w.z; Bs[c4 * 4 + 3][oo] = w.w;
        }
        __syncthreads();
        ginner<8, 4, 132, 132>(As, Bs, acc, tx, ty * 8);
        __syncthreads();
    }

    const int bh0 = blockIdx.z * NH;
#pragma unroll
    for (int q = 0; q < 4; q++)
#pragma unroll
        for (int e = 0; e < 2; e++) {
            int o = o0 + 2 * (tx + 16 * q) + e;
            int h = o / 192, rr = o - h * 192;
            float* dst; int d;
            if (rr < 64)       { dst = g_Q; d = rr; }
            else if (rr < 128) { dst = g_K; d = rr - 64; }
            else               { dst = g_V; d = rr - 128; }
            float bias = bp[o];
            float* base = dst + ((size_t)(bh0 + h) * NDK + d) * NSEQ + n0 + ty * 8;
            float4 v0, v1;
            v0.x = (e ? f2hi(acc[0][q]) : f2lo(acc[0][q])) + bias;
            v0.y = (e ? f2hi(acc[1][q]) : f2lo(acc[1][q])) + bias;
            v0.z = (e ? f2hi(acc[2][q]) : f2lo(acc[2][q])) + bias;
            v0.w = (e ? f2hi(acc[3][q]) : f2lo(acc[3][q])) + bias;
            v1.x = (e ? f2hi(acc[4][q]) : f2lo(acc[4][q])) + bias;
            v1.y = (e ? f2hi(acc[5][q]) : f2lo(acc[5][q])) + bias;
            v1.z = (e ? f2hi(acc[6][q]) : f2lo(acc[6][q])) + bias;
            v1.w = (e ? f2hi(acc[7][q]) : f2lo(acc[7][q])) + bias;
            *(float4*)base = v0; *(float4*)(base + 4) = v1;
        }
}

// ---------- K2a: S = exp(scale * Q^T K) ----------
__global__ void __launch_bounds__(256) k2a_scores() {
    __shared__ float As[16][132];  // [dd][ii] from Q (d-major: direct copy)
    __shared__ float Bs[16][132];  // [dd][jj] from K
    const int tid = threadIdx.x, tx = tid & 15, ty = tid >> 4;
    const int j0 = blockIdx.x * 128, i0 = blockIdx.y * 128, bh = blockIdx.z;
    const float* Qb = g_Q + (size_t)bh * NDK * NSEQ;
    const float* Kb = g_K + (size_t)bh * NDK * NSEQ;

    UL acc[8][4];
#pragma unroll
    for (int m = 0; m < 8; m++)
#pragma unroll
        for (int q = 0; q < 4; q++) acc[m][q] = 0ull;

    for (int d0 = 0; d0 < NDK; d0 += 16) {
#pragma unroll
        for (int r = 0; r < 2; r++) {
            int idx = tid + 256 * r, dd = idx >> 5, f4 = idx & 31;
            *(float4*)&As[dd][f4 * 4] = *(const float4*)(Qb + (size_t)(d0 + dd) * NSEQ + i0 + f4 * 4);
            *(float4*)&Bs[dd][f4 * 4] = *(const float4*)(Kb + (size_t)(d0 + dd) * NSEQ + j0 + f4 * 4);
        }
        __syncthreads();
        ginner<8, 4, 132, 132>(As, Bs, acc, tx, ty * 8);
        __syncthreads();
    }

    float* Sb = g_S + (size_t)bh * NSEQ * NSEQ;
#pragma unroll
    for (int q = 0; q < 4; q++) {
        int jc = j0 + 2 * (tx + 16 * q);
#pragma unroll
        for (int m = 0; m < 8; m++) {
            int i = i0 + ty * 8 + m;
            float2 ev;
            ev.x = __expf(f2lo(acc[m][q]) * 0.125f);
            ev.y = __expf(f2hi(acc[m][q]) * 0.125f);
            *(float2*)(Sb + (size_t)i * NSEQ + jc) = ev;
        }
    }
}

// ---------- K2b: rl[j] = 1 / sum_i S[i][j] (deterministic) ----------
__global__ void __launch_bounds__(256) k2b_colsum() {
    const int bh = blockIdx.y;
    const int j = blockIdx.x * 256 + threadIdx.x;
    const float* Sb = g_S + (size_t)bh * NSEQ * NSEQ + j;
    float s0 = 0.f, s1 = 0.f, s2 = 0.f, s3 = 0.f;
    for (int i = 0; i < NSEQ; i += 4) {
        s0 += Sb[(size_t)(i + 0) * NSEQ];
        s1 += Sb[(size_t)(i + 1) * NSEQ];
        s2 += Sb[(size_t)(i + 2) * NSEQ];
        s3 += Sb[(size_t)(i + 3) * NSEQ];
    }
    g_rl[bh * NSEQ + j] = 1.0f / ((s0 + s1) + (s2 + s3));
}

// ---------- K2c: R^T[d][i] = sum_j (V[d][j]*rl[j]) * S[i][j] ----------
// 128 threads (tx16 x ty8): NM=8 over d (full 64), NQ=4 packed over i (128-tile).
__global__ void __launch_bounds__(128) k2c_av() {
    __shared__ float As[16][68];   // [jj][dd]  V[d][j]*rl[j]
    __shared__ float Bs[16][132];  // [jj][ii]  S transposed tile
    const int tid = threadIdx.x, tx = tid & 15, ty = tid >> 4;
    const int i0 = blockIdx.x * 128, h = blockIdx.y, b = blockIdx.z;
    const int bh = b * NH + h;
    const float* Sb  = g_S + (size_t)bh * NSEQ * NSEQ;
    const float* Vb  = g_V + (size_t)bh * NDK * NSEQ;
    const float* rlb = g_rl + bh * NSEQ;

    UL acc[8][4];
#pragma unroll
    for (int m = 0; m < 8; m++)
#pragma unroll
        for (int q = 0; q < 4; q++) acc[m][q] = 0ull;

    for (int j0 = 0; j0 < NSEQ; j0 += 16) {
        {   // V tile 64d x 16j, scaled by rl, stored transposed [jj][dd]
            int dd = tid & 63, j8 = tid >> 6;  // 2 float4s per thread
#pragma unroll
            for (int s = 0; s < 2; s++) {
                int jj = j8 * 8 + s * 4;
                float4 vv = *(const float4*)(Vb + (size_t)dd * NSEQ + j0 + jj);
                As[jj + 0][dd] = vv.x * rlb[j0 + jj + 0];
                As[jj + 1][dd] = vv.y * rlb[j0 + jj + 1];
                As[jj + 2][dd] = vv.z * rlb[j0 + jj + 2];
                As[jj + 3][dd] = vv.w * rlb[j0 + jj + 3];
            }
        }
#pragma unroll
        for (int r = 0; r < 4; r++) {  // S tile transposed: Bs[jj][ii]
            int idx = tid + 128 * r, ii = idx >> 2, j4 = idx & 3;
            float4 sv = *(const float4*)(Sb + (size_t)(i0 + ii) * NSEQ + j0 + j4 * 4);
            Bs[j4 * 4 + 0][ii] = sv.x; Bs[j4 * 4 + 1][ii] = sv.y;
            Bs[j4 * 4 + 2][ii] = sv.z; Bs[j4 * 4 + 3][ii] = sv.w;
        }
        __syncthreads();
        ginner<8, 4, 68, 132>(As, Bs, acc, tx, ty * 8);
        __syncthreads();
    }

    float* Rb = g_R + ((size_t)b * NC + h * NDK) * NSEQ;
#pragma unroll
    for (int m = 0; m < 8; m++) {
        int d = ty * 8 + m;
#pragma unroll
        for (int q = 0; q < 4; q++) {
            float2 v; v.x = f2lo(acc[m][q]); v.y = f2hi(acc[m][q]);
            *(float2*)(Rb + (size_t)d * NSEQ + i0 + 2 * (tx + 16 * q)) = v;
        }
    }
}

// ---------- K3: out[b][c][n] = sum_k R^T[k][n] * Wo[c][k] + bo[c] + x[b][c][n] ----------
__global__ void __launch_bounds__(256) k3_out(const float* __restrict__ x,
                                              const float* __restrict__ Wo,
                                              const float* __restrict__ bo,
                                              float* __restrict__ out) {
    __shared__ float As[16][132];  // [kk][nn] from R^T (c-major: direct copy)
    __shared__ float Bs[16][132];  // [kk][cc] from Wo (transposed on load)
    const int tid = threadIdx.x, tx = tid & 15, ty = tid >> 4;
    const int n0 = blockIdx.x * 128, c0 = blockIdx.y * 128, b = blockIdx.z;
    const float* Rb = g_R + (size_t)b * NC * NSEQ;

    UL acc[8][4];
#pragma unroll
    for (int m = 0; m < 8; m++)
#pragma unroll
        for (int q = 0; q < 4; q++) acc[m][q] = 0ull;

    for (int k0 = 0; k0 < NC; k0 += 16) {
#pragma unroll
        for (int r = 0; r < 2; r++) {
            int idx = tid + 256 * r, kk = idx >> 5, f4 = idx & 31;
            *(float4*)&As[kk][f4 * 4] = *(const float4*)(Rb + (size_t)(k0 + kk) * NSEQ + n0 + f4 * 4);
        }
#pragma unroll
        for (int r = 0; r < 2; r++) {
            int idx = tid + 256 * r, cc = idx >> 2, c4 = idx & 3;
            float4 wv = *(const float4*)(Wo + (size_t)(c0 + cc) * NC + k0 + c4 * 4);
            Bs[c4 * 4 + 0][cc] = wv.x; Bs[c4 * 4 + 1][cc] = wv.y;
            Bs[c4 * 4 + 2][cc] = wv.z; Bs[c4 * 4 + 3][cc] = wv.w;
        }
        __syncthreads();
        ginner<8, 4, 132, 132>(As, Bs, acc, tx, ty * 8);
        __syncthreads();
    }

#pragma unroll
    for (int q = 0; q < 4; q++)
#pragma unroll
        for (int e = 0; e < 2; e++) {
            int c = c0 + 2 * (tx + 16 * q) + e;
            float bias = bo[c];
            const float* xr = x + ((size_t)b * NC + c) * NSEQ + n0 + ty * 8;
            float* orow = out + ((size_t)b * NC + c) * NSEQ + n0 + ty * 8;
            float4 x0 = *(const float4*)xr, x1 = *(const float4*)(xr + 4);
            float4 v0, v1;
            v0.x = (e ? f2hi(acc[0][q]) : f2lo(acc[0][q])) + bias + x0.x;
            v0.y = (e ? f2hi(acc[1][q]) : f2lo(acc[1][q])) + bias + x0.y;
            v0.z = (e ? f2hi(acc[2][q]) : f2lo(acc[2][q])) + bias + x0.z;
            v0.w = (e ? f2hi(acc[3][q]) : f2lo(acc[3][q])) + bias + x0.w;
            v1.x = (e ? f2hi(acc[4][q]) : f2lo(acc[4][q])) + bias + x1.x;
            v1.y = (e ? f2hi(acc[5][q]) : f2lo(acc[5][q])) + bias + x1.y;
            v1.z = (e ? f2hi(acc[6][q]) : f2lo(acc[6][q])) + bias + x1.z;
            v1.w = (e ? f2hi(acc[7][q]) : f2lo(acc[7][q])) + bias + x1.w;
            *(float4*)orow = v0; *(float4*)(orow + 4) = v1;
        }
}

extern "C" void kernel_launch(void* const* d_in, const int* in_sizes, int n_in,
                              void* d_out, int out_size) {
    const float* x  = (const float*)d_in[0];
    const float* Wp = (const float*)d_in[1];
    const float* bp = (const float*)d_in[2];
    const float* Wo = (const float*)d_in[3];
    const float* bo = (const float*)d_in[4];
    float* out = (float*)d_out;

    k1_qkv<<<dim3(NSEQ / 128, (3 * NH * NDK) / 128, NB), 256>>>(x, Wp, bp);
    k2a_scores<<<dim3(NSEQ / 128, NSEQ / 128, NBH), 256>>>();
    k2b_colsum<<<dim3(NSEQ / 256, NBH), 256>>>();
    k2c_av<<<dim3(NSEQ / 128, NH, NB), 128>>>();
    k3_out<<<dim3(NSEQ / 128, NC / 128, NB), 256>>>(x, Wo, bo, out);
}